// round 11
// baseline (speedup 1.0000x reference)
#include <cuda_runtime.h>
#include <cuda_bf16.h>
#include <math.h>
#include <float.h>
#include <stdint.h>

// ============================================================================
// KNN classifier, R8 (= R7 resubmit; R7 never ran — GB300 broker infra flake):
// int8 IMMA prefilter GEMM (2x HMMA rate) + exact fp32 rescore.
// (tcgen05 unusable: harness compiles at compute_103, no 'a'.)
//   1) per-row symmetric int8 quantization of A and B (exact s32 accumulate)
//   2) sim_approx = (Aq.Bq) * ra[m] * rb[n]  via mma.sync.m16n8k32.s8
//   3) per row: histogram -> rank-200 bin -> single-pass dual-tier candidate
//      collect (margin 3.0) -> exact fp32 rescore -> top-200 sort ->
//      softmax(T=.07) -> 4 class histograms
// Precision: prefilter noise sigma~0.43 (quant 0.40 + bf16 store 0.15);
// only neighbors within ~0.64 of the row max carry softmax weight; margin
// 3.0 = 5.5 sigma of slack. Final sims are exact fp32.
// ============================================================================

#define NQ    2048
#define NT    100000
#define DIM   1024
#define NCLS  1000
#define MAXK  200
#define TINV  (1.0f / 0.07f)

__device__ __nv_bfloat16 g_simh[(size_t)NQ * NT];   // 409.6 MB approx sims
__device__ int8_t g_qA[(size_t)NQ * DIM];           // 2 MB
__device__ int8_t g_qB[(size_t)NT * DIM];           // 102.4 MB
__device__ float  g_ra[NQ];                         // 1/scale per A row
__device__ float  g_rb[NT];                         // 1/scale per B row

__device__ __forceinline__ uint32_t smem_u32(const void* p) {
    uint32_t a;
    asm("{ .reg .u64 t; cvta.to.shared.u64 t, %1; cvt.u32.u64 %0, t; }"
        : "=r"(a) : "l"(p));
    return a;
}
#define CP_ASYNC16(dst, src) \
    asm volatile("cp.async.ca.shared.global [%0], [%1], 16;" \
                 :: "r"(dst), "l"(src) : "memory")
#define CP_ASYNC16_Z(dst, src, sz) \
    asm volatile("cp.async.ca.shared.global [%0], [%1], 16, %2;" \
                 :: "r"(dst), "l"(src), "r"(sz) : "memory")
#define CP_COMMIT() asm volatile("cp.async.commit_group;" ::: "memory")
#define CP_WAIT(n)  asm volatile("cp.async.wait_group %0;" :: "n"(n) : "memory")

// ---------------------------------------------------------------------------
// per-row symmetric int8 quantization (one warp per row)
// ---------------------------------------------------------------------------
__global__ void quant_s8(const float* __restrict__ src, int8_t* __restrict__ dst,
                         float* __restrict__ rscale, int nrows)
{
    const int w = (blockIdx.x * blockDim.x + threadIdx.x) >> 5;
    const int lane = threadIdx.x & 31;
    if (w >= nrows) return;
    const float4* s = (const float4*)(src + (size_t)w * DIM);
    float4 v[8];
    float mx = 0.f;
    #pragma unroll
    for (int j = 0; j < 8; j++) {
        v[j] = s[j * 32 + lane];
        mx = fmaxf(mx, fmaxf(fmaxf(fabsf(v[j].x), fabsf(v[j].y)),
                             fmaxf(fabsf(v[j].z), fabsf(v[j].w))));
    }
    #pragma unroll
    for (int o = 16; o > 0; o >>= 1) mx = fmaxf(mx, __shfl_xor_sync(~0u, mx, o));
    const float sc = 127.0f / fmaxf(mx, 1e-20f);
    if (lane == 0) rscale[w] = fmaxf(mx, 1e-20f) * (1.0f / 127.0f);
    char4* d = (char4*)(dst + (size_t)w * DIM);
    #pragma unroll
    for (int j = 0; j < 8; j++) {
        char4 c;
        c.x = (char)__float2int_rn(v[j].x * sc);
        c.y = (char)__float2int_rn(v[j].y * sc);
        c.z = (char)__float2int_rn(v[j].z * sc);
        c.w = (char)__float2int_rn(v[j].w * sc);
        d[j * 32 + lane] = c;
    }
}

// ---------------------------------------------------------------------------
// int8 GEMM: C[m,n] = sum_k Aq[m,k]Bq[n,k] via mma.sync m16n8k32.s8 (row.col).
// 128x128 tile, BK=64 bytes, 256 thr = 8 warps (2M x 4N), warp tile 64x32.
// Double-buffered cp.async; row stride 80B => ldmatrix conflict-free
// (identical byte geometry to the R6 bf16 kernel: 16B quadrants, banks
// {0,20,8,28,16,4,24,12} across 8 rows).
// ---------------------------------------------------------------------------
#define BM 128
#define BN 128
#define BKB 64                 // k-bytes per chunk (64 s8)
#define RS  80                 // padded row stride in bytes
#define NCHK (DIM / BKB)       // 16

__global__ void __launch_bounds__(256)
gemm_imma(const int8_t* __restrict__ Aq, const int8_t* __restrict__ Bq,
          const float* __restrict__ ra, const float* __restrict__ rb)
{
    __shared__ int8_t As[2][BM * RS];
    __shared__ int8_t Bs[2][BN * RS];

    const int tid  = threadIdx.x;
    const int lane = tid & 31;
    const int wid  = tid >> 5;
    const int wm   = wid & 1;          // 0..1  (64-row block)
    const int wn   = wid >> 1;         // 0..3  (32-col block)
    const int m0   = blockIdx.x * BM;
    const int n0   = blockIdx.y * BN;

    const uint32_t sA[2] = { smem_u32(&As[0][0]), smem_u32(&As[1][0]) };
    const uint32_t sB[2] = { smem_u32(&Bs[0][0]), smem_u32(&Bs[1][0]) };

    int acc[4][4][4];
    #pragma unroll
    for (int i = 0; i < 4; i++)
        #pragma unroll
        for (int j = 0; j < 4; j++)
            #pragma unroll
            for (int q = 0; q < 4; q++) acc[i][j][q] = 0;

    // tile loader: 512 16B-chunks each for A and B; 4 chunks per thread total
    auto load_tile = [&](int buf, int k0) {
        #pragma unroll
        for (int p = 0; p < 2; p++) {
            const int cid = tid + p * 256;
            const int r = cid >> 2, cc = cid & 3;
            const uint32_t da = sA[buf] + (uint32_t)(r * RS + cc * 16);
            CP_ASYNC16(da, Aq + (size_t)(m0 + r) * DIM + k0 + cc * 16);
            const int n = n0 + r;
            const int ncl = n < NT ? n : NT - 1;
            const uint32_t db = sB[buf] + (uint32_t)(r * RS + cc * 16);
            CP_ASYNC16_Z(db, Bq + (size_t)ncl * DIM + k0 + cc * 16,
                         n < NT ? 16u : 0u);
        }
    };

    load_tile(0, 0);
    CP_COMMIT();

    for (int kc = 0; kc < NCHK; kc++) {
        const int buf = kc & 1;
        __syncthreads();                     // other buffer free for reload
        if (kc + 1 < NCHK) {
            load_tile(buf ^ 1, (kc + 1) * BKB);
            CP_COMMIT();
            CP_WAIT(1);                      // tile kc landed; kc+1 in flight
        } else {
            CP_WAIT(0);
        }
        __syncthreads();                     // tile kc visible to all

        #pragma unroll
        for (int ks = 0; ks < 2; ks++) {     // two k32 steps per 64B chunk
            uint32_t a[4][4];
            #pragma unroll
            for (int mf = 0; mf < 4; mf++) {
                const int row = wm * 64 + mf * 16 + (lane & 15);
                const uint32_t addr = sA[buf]
                    + (uint32_t)(row * RS + ks * 32 + (lane >> 4) * 16);
                asm volatile("ldmatrix.sync.aligned.m8n8.x4.shared.b16 "
                             "{%0,%1,%2,%3}, [%4];"
                             : "=r"(a[mf][0]), "=r"(a[mf][1]),
                               "=r"(a[mf][2]), "=r"(a[mf][3]) : "r"(addr));
            }
            uint32_t b[4][2];
            #pragma unroll
            for (int nf = 0; nf < 4; nf++) {
                const int row = wn * 32 + nf * 8 + (lane & 7);
                const uint32_t addr = sB[buf]
                    + (uint32_t)(row * RS + ks * 32 + ((lane >> 3) & 1) * 16);
                asm volatile("ldmatrix.sync.aligned.m8n8.x2.shared.b16 "
                             "{%0,%1}, [%2];"
                             : "=r"(b[nf][0]), "=r"(b[nf][1]) : "r"(addr));
            }
            #pragma unroll
            for (int mf = 0; mf < 4; mf++)
                #pragma unroll
                for (int nf = 0; nf < 4; nf++)
                    asm volatile(
                        "mma.sync.aligned.m16n8k32.row.col.s32.s8.s8.s32 "
                        "{%0,%1,%2,%3}, {%4,%5,%6,%7}, {%8,%9}, {%0,%1,%2,%3};"
                        : "+r"(acc[mf][nf][0]), "+r"(acc[mf][nf][1]),
                          "+r"(acc[mf][nf][2]), "+r"(acc[mf][nf][3])
                        : "r"(a[mf][0]), "r"(a[mf][1]), "r"(a[mf][2]), "r"(a[mf][3]),
                          "r"(b[nf][0]), "r"(b[nf][1]));
        }
    }

    // epilogue: dequant (sim = acc * ra[m] * rb[n]) -> bf16x2 direct stores
    #pragma unroll
    for (int mf = 0; mf < 4; mf++) {
        const int m = m0 + wm * 64 + mf * 16 + (lane >> 2);
        const float ram  = __ldg(ra + m);
        const float ram8 = __ldg(ra + m + 8);
        #pragma unroll
        for (int nf = 0; nf < 4; nf++) {
            const int n = n0 + wn * 32 + nf * 8 + (lane & 3) * 2;
            if (n < NT) {
                const float rbn  = __ldg(rb + n);
                const float rbn1 = __ldg(rb + n + 1);
                __nv_bfloat162 h0 = __float22bfloat162_rn(make_float2(
                    (float)acc[mf][nf][0] * ram * rbn,
                    (float)acc[mf][nf][1] * ram * rbn1));
                __nv_bfloat162 h1 = __float22bfloat162_rn(make_float2(
                    (float)acc[mf][nf][2] * ram8 * rbn,
                    (float)acc[mf][nf][3] * ram8 * rbn1));
                *(uint32_t*)(g_simh + (size_t)m * NT + n)       = *(uint32_t*)&h0;
                *(uint32_t*)(g_simh + (size_t)(m + 8) * NT + n) = *(uint32_t*)&h1;
            }
        }
    }
}

// ---------------------------------------------------------------------------
// Pass 2: per-row candidate select + exact rescore + topk + softmax + hist
// ---------------------------------------------------------------------------
#define NBINS 4096
#define HLO   (-256.0f)
#define HSC   8.0f
#define CAND  512
#define CORE_CAP 384
#define MARG_CAP 128
#define NTHR  256
#define MARGIN_BINS 24          // 3.0 sim units (int8 prefilter noise ~0.43)

__device__ __forceinline__ int bin_of(float v)
{
    int b = (int)((v - HLO) * HSC);
    return min(max(b, 0), NBINS - 1);
}

__global__ void __launch_bounds__(NTHR)
topk_kernel(const float* __restrict__ A, const float* __restrict__ B,
            const int* __restrict__ labels, float* __restrict__ out)
{
    const int row = blockIdx.x;
    const int tid = threadIdx.x;
    const uint4* simv = (const uint4*)(g_simh + (size_t)row * NT);   // 8 bf16 each

    __shared__ unsigned hist[NBINS];
    __shared__ int   cidx[CAND];
    __shared__ float cval[CAND];
    __shared__ unsigned long long ckey[CAND];
    __shared__ __align__(16) float arow[DIM];
    __shared__ float prob[NCLS];
    __shared__ float wgt[MAXK];
    __shared__ int   lab[MAXK];
    __shared__ float s_red[NTHR];
    __shared__ int   s_core, s_marg, s_bstar;

    for (int i = tid; i < DIM; i += NTHR) arow[i] = A[(size_t)row * DIM + i];
    for (int b = tid; b < NBINS; b += NTHR) hist[b] = 0;
    if (tid == 0) { s_core = 0; s_marg = 0; }
    __syncthreads();

    // Phase 1: histogram of approx sims
    for (int i = tid; i < NT / 8; i += NTHR) {
        uint4 v = simv[i];
        const uint32_t w[4] = { v.x, v.y, v.z, v.w };
        #pragma unroll
        for (int q = 0; q < 4; q++) {
            __nv_bfloat162 h = *(const __nv_bfloat162*)&w[q];
            atomicAdd(&hist[bin_of(__bfloat162float(h.x))], 1u);
            atomicAdd(&hist[bin_of(__bfloat162float(h.y))], 1u);
        }
    }
    __syncthreads();

    // Phase 2: rank-200 bin
    if (tid == 0) {
        unsigned cum = 0; int b = NBINS - 1;
        while (b >= 0) { cum += hist[b]; if (cum >= MAXK) break; b--; }
        s_bstar = (b < 0) ? 0 : b;
    }
    __syncthreads();
    const int bstar = s_bstar;
    const int bthr  = max(bstar - MARGIN_BINS, 0);

    // Phase 3: single-pass dual-region collect
    //   core (b >= bstar)    -> slots [0, CORE_CAP)
    //   margin (bthr..bstar) -> slots [CORE_CAP, CAND)
    for (int i = tid; i < NT / 8; i += NTHR) {
        uint4 v = simv[i];
        const uint32_t w[4] = { v.x, v.y, v.z, v.w };
        #pragma unroll
        for (int q = 0; q < 8; q++) {
            __nv_bfloat16 h = ((const __nv_bfloat16*)w)[q];
            const int b = bin_of(__bfloat162float(h));
            if (b >= bstar) {
                const int p = atomicAdd(&s_core, 1);
                if (p < CORE_CAP) cidx[p] = i * 8 + q;
            } else if (b >= bthr) {
                const int p = atomicAdd(&s_marg, 1);
                if (p < MARG_CAP) cidx[CORE_CAP + p] = i * 8 + q;
            }
        }
    }
    __syncthreads();
    const int core = min(s_core, CORE_CAP);
    const int marg = min(s_marg, MARG_CAP);
    // compact margin region to [core, core+marg)
    int mv = 0;
    if (tid < marg) mv = cidx[CORE_CAP + tid];
    __syncthreads();
    if (tid < marg) cidx[core + tid] = mv;
    __syncthreads();
    const int cnt = core + marg;

    // Phase 4: exact fp32 rescore (one candidate per warp)
    const int lane = tid & 31, wrp = tid >> 5;
    const float4* a4 = (const float4*)arow;
    for (int c = wrp; c < cnt; c += 8) {
        const float4* b4 = (const float4*)(B + (size_t)cidx[c] * DIM);
        float acc = 0.f;
        #pragma unroll
        for (int j = 0; j < 8; j++) {
            const int k4 = j * 32 + lane;
            float4 bb = b4[k4], aa = a4[k4];
            acc = fmaf(aa.x, bb.x, acc); acc = fmaf(aa.y, bb.y, acc);
            acc = fmaf(aa.z, bb.z, acc); acc = fmaf(aa.w, bb.w, acc);
        }
        #pragma unroll
        for (int o = 16; o > 0; o >>= 1) acc += __shfl_down_sync(0xffffffffu, acc, o);
        if (lane == 0) cval[c] = acc;
    }
    __syncthreads();

    // Phase 5: sort keys (value desc, index asc — jax top_k order)
    for (int i = tid; i < CAND; i += NTHR) {
        if (i < cnt) {
            unsigned u = __float_as_uint(cval[i]);
            unsigned s = (u & 0x80000000u) ? ~u : (u | 0x80000000u);
            ckey[i] = ((unsigned long long)s << 32) | (unsigned)(~(unsigned)cidx[i]);
        } else ckey[i] = 0ull;
    }
    __syncthreads();

    for (int ksz = 2; ksz <= CAND; ksz <<= 1)
        for (int st = ksz >> 1; st > 0; st >>= 1) {
            for (int j = tid; j < CAND; j += NTHR) {
                const int ixj = j ^ st;
                if (ixj > j) {
                    const unsigned long long a = ckey[j], b = ckey[ixj];
                    const bool desc = ((j & ksz) == 0);
                    if (desc ? (a < b) : (a > b)) { ckey[j] = b; ckey[ixj] = a; }
                }
            }
            __syncthreads();
        }

    // Phase 6: softmax over top-200
    float maxv;
    {
        const unsigned s0 = (unsigned)(ckey[0] >> 32);
        const unsigned u0 = (s0 & 0x80000000u) ? (s0 & 0x7fffffffu) : ~s0;
        maxv = __uint_as_float(u0);
    }
    float wv = 0.f;
    if (tid < MAXK) {
        const unsigned long long k = ckey[tid];
        const unsigned s = (unsigned)(k >> 32);
        const unsigned u = (s & 0x80000000u) ? (s & 0x7fffffffu) : ~s;
        const float v = __uint_as_float(u);
        const int idx = (int)(~(unsigned)k);
        wv = expf((v - maxv) * TINV);
        wgt[tid] = wv;
        lab[tid] = labels[idx];
    }
    s_red[tid] = wv;
    __syncthreads();
    for (int off = NTHR / 2; off > 0; off >>= 1) {
        if (tid < off) s_red[tid] += s_red[tid + off];
        __syncthreads();
    }
    const float inv = 1.0f / s_red[0];

    // Phase 7: 4 prefix class-histograms
    const int KS[4] = { 10, 20, 100, 200 };
    #pragma unroll
    for (int kk = 0; kk < 4; kk++) {
        for (int c = tid; c < NCLS; c += NTHR) prob[c] = 0.f;
        __syncthreads();
        if (tid < KS[kk]) atomicAdd(&prob[lab[tid]], wgt[tid] * inv);
        __syncthreads();
        float* o = out + ((size_t)kk * NQ + row) * NCLS;
        for (int c = tid; c < NCLS; c += NTHR) o[c] = prob[c];
        __syncthreads();
    }
}

// ---------------------------------------------------------------------------
extern "C" void kernel_launch(void* const* d_in, const int* in_sizes, int n_in,
                              void* d_out, int out_size)
{
    const float* A      = (const float*)d_in[0];   // [2048,1024]
    const float* B      = (const float*)d_in[1];   // [100000,1024]
    const int*   labels = (const int*)d_in[2];     // [100000]
    float*       out    = (float*)d_out;           // 4 x [2048,1000]

    int8_t *qA, *qB;
    float  *ra, *rb;
    cudaGetSymbolAddress((void**)&qA, g_qA);
    cudaGetSymbolAddress((void**)&qB, g_qB);
    cudaGetSymbolAddress((void**)&ra, g_ra);
    cudaGetSymbolAddress((void**)&rb, g_rb);

    quant_s8<<<(NQ * 32 + 255) / 256, 256>>>(A, qA, ra, NQ);
    quant_s8<<<(NT * 32 + 255) / 256, 256>>>(B, qB, rb, NT);

    dim3 grid(NQ / BM, (NT + BN - 1) / BN);        // 16 x 782
    gemm_imma<<<grid, 256>>>(qA, qB, ra, rb);

    topk_kernel<<<NQ, NTHR>>>(A, B, labels, out);
}

// round 15
// speedup vs baseline: 1.2463x; 1.2463x over previous
#include <cuda_runtime.h>
#include <cuda_bf16.h>
#include <math.h>
#include <float.h>
#include <stdint.h>

// ============================================================================
// KNN classifier, R12: bf16 HMMA prefilter GEMM (reverted from IMMA — measured
// s8 mma.sync at ~half bf16 rate on sm_103) + exact fp32 rescore, with
// chunked GEMM/topk OVERLAP on a second stream (event fork/join, capture-legal).
//   1) convert A,B fp32 -> bf16
//   2) sim_approx chunk c (256 rows) = bf16 GEMM via mma.sync.m16n8k16
//   3) topk(chunk c) runs on side stream concurrent with GEMM(chunk c+1):
//      histogram -> rank-200 bin -> single-pass dual-tier collect (margin 1.0)
//      -> exact fp32 rescore -> top-200 sort -> softmax(T=.07) -> 4 histograms
// Output depends only on the exact fp32 rescore (verified: rel_err identical
// across int8 and bf16 prefilters) — prefilter only needs containment.
// ============================================================================

#define NQ    2048
#define NT    100000
#define DIM   1024
#define NCLS  1000
#define MAXK  200
#define TINV  (1.0f / 0.07f)

#define NCHUNK       8
#define MT_PER_CHUNK 2                     // M-tiles (of 128) per chunk
#define ROWS_PER_CHUNK (NQ / NCHUNK)       // 256

__device__ __nv_bfloat16 g_simh[(size_t)NQ * NT];     // 409.6 MB approx sims
__device__ __nv_bfloat16 g_bA[(size_t)NQ * DIM];      // 4 MB
__device__ __nv_bfloat16 g_bB[(size_t)NT * DIM];      // 204.8 MB

__device__ __forceinline__ uint32_t smem_u32(const void* p) {
    uint32_t a;
    asm("{ .reg .u64 t; cvta.to.shared.u64 t, %1; cvt.u32.u64 %0, t; }"
        : "=r"(a) : "l"(p));
    return a;
}
#define CP_ASYNC16(dst, src) \
    asm volatile("cp.async.ca.shared.global [%0], [%1], 16;" \
                 :: "r"(dst), "l"(src) : "memory")
#define CP_ASYNC16_Z(dst, src, sz) \
    asm volatile("cp.async.ca.shared.global [%0], [%1], 16, %2;" \
                 :: "r"(dst), "l"(src), "r"(sz) : "memory")
#define CP_COMMIT() asm volatile("cp.async.commit_group;" ::: "memory")
#define CP_WAIT(n)  asm volatile("cp.async.wait_group %0;" :: "n"(n) : "memory")

// ---------------------------------------------------------------------------
// fp32 -> bf16 converter (8 elems/thread)
// ---------------------------------------------------------------------------
__global__ void conv_bf16(const float* __restrict__ src,
                          __nv_bfloat16* __restrict__ dst, int n8)
{
    int i = blockIdx.x * 256 + threadIdx.x;
    if (i >= n8) return;
    const float4* s = (const float4*)src;
    float4 v0 = s[2 * i], v1 = s[2 * i + 1];
    __nv_bfloat162 h0 = __float22bfloat162_rn(make_float2(v0.x, v0.y));
    __nv_bfloat162 h1 = __float22bfloat162_rn(make_float2(v0.z, v0.w));
    __nv_bfloat162 h2 = __float22bfloat162_rn(make_float2(v1.x, v1.y));
    __nv_bfloat162 h3 = __float22bfloat162_rn(make_float2(v1.z, v1.w));
    uint4 o;
    o.x = *(uint32_t*)&h0; o.y = *(uint32_t*)&h1;
    o.z = *(uint32_t*)&h2; o.w = *(uint32_t*)&h3;
    ((uint4*)dst)[i] = o;
}

// ---------------------------------------------------------------------------
// bf16 GEMM (per-chunk): C[m,n] = sum_k A[m,k]B[n,k] via mma.sync m16n8k16.
// 128x128 tile, BK=32, 256 thr = 8 warps (2M x 4N), warp tile 64x32.
// Double-buffered cp.async; padded SMEM stride (40 bf16) => ldmatrix
// conflict-free. mt_base selects the chunk's M-tiles.
// ---------------------------------------------------------------------------
#define BM 128
#define BN 128
#define BK 32
#define KPAD 40
#define NCHK (DIM / BK)        // 32

__global__ void __launch_bounds__(256)
gemm_mma(const __nv_bfloat16* __restrict__ Ab, const __nv_bfloat16* __restrict__ Bb,
         int mt_base)
{
    __shared__ __nv_bfloat16 As[2][BM * KPAD];
    __shared__ __nv_bfloat16 Bs[2][BN * KPAD];

    const int tid  = threadIdx.x;
    const int lane = tid & 31;
    const int wid  = tid >> 5;
    const int wm   = wid & 1;          // 0..1  (64-row block)
    const int wn   = wid >> 1;         // 0..3  (32-col block)
    const int m0   = (mt_base + blockIdx.x) * BM;
    const int n0   = blockIdx.y * BN;

    const uint32_t sA[2] = { smem_u32(&As[0][0]), smem_u32(&As[1][0]) };
    const uint32_t sB[2] = { smem_u32(&Bs[0][0]), smem_u32(&Bs[1][0]) };

    float acc[4][4][4];
    #pragma unroll
    for (int i = 0; i < 4; i++)
        #pragma unroll
        for (int j = 0; j < 4; j++)
            #pragma unroll
            for (int q = 0; q < 4; q++) acc[i][j][q] = 0.f;

    auto load_tile = [&](int buf, int k0) {
        #pragma unroll
        for (int p = 0; p < 2; p++) {
            const int cid = tid + p * 256;
            const int r = cid >> 2, cc = cid & 3;
            const uint32_t da = sA[buf] + (uint32_t)(r * KPAD + cc * 8) * 2;
            CP_ASYNC16(da, Ab + (size_t)(m0 + r) * DIM + k0 + cc * 8);
            const int n = n0 + r;
            const int ncl = n < NT ? n : NT - 1;
            const uint32_t db = sB[buf] + (uint32_t)(r * KPAD + cc * 8) * 2;
            CP_ASYNC16_Z(db, Bb + (size_t)ncl * DIM + k0 + cc * 8,
                         n < NT ? 16u : 0u);
        }
    };

    load_tile(0, 0);
    CP_COMMIT();

    for (int kc = 0; kc < NCHK; kc++) {
        const int buf = kc & 1;
        __syncthreads();
        if (kc + 1 < NCHK) {
            load_tile(buf ^ 1, (kc + 1) * BK);
            CP_COMMIT();
            CP_WAIT(1);
        } else {
            CP_WAIT(0);
        }
        __syncthreads();

        #pragma unroll
        for (int ks = 0; ks < 2; ks++) {
            uint32_t a[4][4];
            #pragma unroll
            for (int mf = 0; mf < 4; mf++) {
                const int row = wm * 64 + mf * 16 + (lane & 15);
                const int col = ks * 16 + (lane >> 4) * 8;
                const uint32_t addr = sA[buf] + (uint32_t)(row * KPAD + col) * 2;
                asm volatile("ldmatrix.sync.aligned.m8n8.x4.shared.b16 "
                             "{%0,%1,%2,%3}, [%4];"
                             : "=r"(a[mf][0]), "=r"(a[mf][1]),
                               "=r"(a[mf][2]), "=r"(a[mf][3]) : "r"(addr));
            }
            uint32_t b[4][2];
            #pragma unroll
            for (int nf = 0; nf < 4; nf++) {
                const int row = wn * 32 + nf * 8 + (lane & 7);
                const int col = ks * 16 + ((lane >> 3) & 1) * 8;
                const uint32_t addr = sB[buf] + (uint32_t)(row * KPAD + col) * 2;
                asm volatile("ldmatrix.sync.aligned.m8n8.x2.shared.b16 "
                             "{%0,%1}, [%2];"
                             : "=r"(b[nf][0]), "=r"(b[nf][1]) : "r"(addr));
            }
            #pragma unroll
            for (int mf = 0; mf < 4; mf++)
                #pragma unroll
                for (int nf = 0; nf < 4; nf++)
                    asm volatile(
                        "mma.sync.aligned.m16n8k16.row.col.f32.bf16.bf16.f32 "
                        "{%0,%1,%2,%3}, {%4,%5,%6,%7}, {%8,%9}, {%0,%1,%2,%3};"
                        : "+f"(acc[mf][nf][0]), "+f"(acc[mf][nf][1]),
                          "+f"(acc[mf][nf][2]), "+f"(acc[mf][nf][3])
                        : "r"(a[mf][0]), "r"(a[mf][1]), "r"(a[mf][2]), "r"(a[mf][3]),
                          "r"(b[nf][0]), "r"(b[nf][1]));
        }
    }

    #pragma unroll
    for (int mf = 0; mf < 4; mf++) {
        const int m = m0 + wm * 64 + mf * 16 + (lane >> 2);
        #pragma unroll
        for (int nf = 0; nf < 4; nf++) {
            const int n = n0 + wn * 32 + nf * 8 + (lane & 3) * 2;
            if (n < NT) {
                __nv_bfloat162 h0 = __float22bfloat162_rn(
                    make_float2(acc[mf][nf][0], acc[mf][nf][1]));
                __nv_bfloat162 h1 = __float22bfloat162_rn(
                    make_float2(acc[mf][nf][2], acc[mf][nf][3]));
                *(uint32_t*)(g_simh + (size_t)m * NT + n)       = *(uint32_t*)&h0;
                *(uint32_t*)(g_simh + (size_t)(m + 8) * NT + n) = *(uint32_t*)&h1;
            }
        }
    }
}

// ---------------------------------------------------------------------------
// Pass 2 (per chunk): candidate select + exact rescore + topk + softmax + hist
// bf16 -> f32 decode is pure bit-shift (no CVT); launch_bounds forces 6
// blocks/SM (R11 measured occ 44.8%, register-limited at 4 blocks).
// ---------------------------------------------------------------------------
#define NBINS 4096
#define HSC   8.0f              // bin = v*8 + 2048, covers [-256, 256)
#define CAND  512
#define CORE_CAP 384
#define MARG_CAP 128
#define NTHR  256
#define MARGIN_BINS 8           // 1.0 sim units (bf16 prefilter noise ~0.15)

__device__ __forceinline__ int bin_of(float v)
{
    int b = (int)fmaf(v, HSC, 2048.0f);
    return min(max(b, 0), NBINS - 1);
}
__device__ __forceinline__ float bf16lo(uint32_t w) { return __uint_as_float(w << 16); }
__device__ __forceinline__ float bf16hi(uint32_t w) { return __uint_as_float(w & 0xFFFF0000u); }

__global__ void __launch_bounds__(NTHR, 6)
topk_kernel(const float* __restrict__ A, const float* __restrict__ B,
            const int* __restrict__ labels, float* __restrict__ out, int row_base)
{
    const int row = row_base + blockIdx.x;
    const int tid = threadIdx.x;
    const uint4* simv = (const uint4*)(g_simh + (size_t)row * NT);   // 8 bf16 each

    __shared__ unsigned hist[NBINS];
    __shared__ int   cidx[CAND];
    __shared__ float cval[CAND];
    __shared__ unsigned long long ckey[CAND];
    __shared__ __align__(16) float arow[DIM];
    __shared__ float prob[NCLS];
    __shared__ float wgt[MAXK];
    __shared__ int   lab[MAXK];
    __shared__ float s_red[NTHR];
    __shared__ int   s_core, s_marg, s_bstar;

    for (int i = tid; i < DIM; i += NTHR) arow[i] = A[(size_t)row * DIM + i];
    for (int b = tid; b < NBINS; b += NTHR) hist[b] = 0;
    if (tid == 0) { s_core = 0; s_marg = 0; }
    __syncthreads();

    // Phase 1: histogram of approx sims (bit-shift decode, no CVT)
    for (int i = tid; i < NT / 8; i += NTHR) {
        uint4 v = simv[i];
        const uint32_t w[4] = { v.x, v.y, v.z, v.w };
        #pragma unroll
        for (int q = 0; q < 4; q++) {
            atomicAdd(&hist[bin_of(bf16lo(w[q]))], 1u);
            atomicAdd(&hist[bin_of(bf16hi(w[q]))], 1u);
        }
    }
    __syncthreads();

    // Phase 2: rank-200 bin
    if (tid == 0) {
        unsigned cum = 0; int b = NBINS - 1;
        while (b >= 0) { cum += hist[b]; if (cum >= MAXK) break; b--; }
        s_bstar = (b < 0) ? 0 : b;
    }
    __syncthreads();
    const int bstar = s_bstar;
    const int bthr  = max(bstar - MARGIN_BINS, 0);

    // Phase 3: single-pass dual-region collect
    for (int i = tid; i < NT / 8; i += NTHR) {
        uint4 v = simv[i];
        const uint32_t w[4] = { v.x, v.y, v.z, v.w };
        #pragma unroll
        for (int q = 0; q < 8; q++) {
            const uint32_t ww = w[q >> 1];
            const float f = (q & 1) ? bf16hi(ww) : bf16lo(ww);
            const int b = bin_of(f);
            if (b >= bstar) {
                const int p = atomicAdd(&s_core, 1);
                if (p < CORE_CAP) cidx[p] = i * 8 + (q >> 1) * 2 + (q & 1);
            } else if (b >= bthr) {
                const int p = atomicAdd(&s_marg, 1);
                if (p < MARG_CAP) cidx[CORE_CAP + p] = i * 8 + (q >> 1) * 2 + (q & 1);
            }
        }
    }
    __syncthreads();
    const int core = min(s_core, CORE_CAP);
    const int marg = min(s_marg, MARG_CAP);
    int mv = 0;
    if (tid < marg) mv = cidx[CORE_CAP + tid];
    __syncthreads();
    if (tid < marg) cidx[core + tid] = mv;
    __syncthreads();
    const int cnt = core + marg;

    // Phase 4: exact fp32 rescore (one candidate per warp)
    const int lane = tid & 31, wrp = tid >> 5;
    const float4* a4 = (const float4*)arow;
    for (int c = wrp; c < cnt; c += 8) {
        const float4* b4 = (const float4*)(B + (size_t)cidx[c] * DIM);
        float acc = 0.f;
        #pragma unroll
        for (int j = 0; j < 8; j++) {
            const int k4 = j * 32 + lane;
            float4 bb = b4[k4], aa = a4[k4];
            acc = fmaf(aa.x, bb.x, acc); acc = fmaf(aa.y, bb.y, acc);
            acc = fmaf(aa.z, bb.z, acc); acc = fmaf(aa.w, bb.w, acc);
        }
        #pragma unroll
        for (int o = 16; o > 0; o >>= 1) acc += __shfl_down_sync(0xffffffffu, acc, o);
        if (lane == 0) cval[c] = acc;
    }
    __syncthreads();

    // Phase 5: sort keys (value desc, index asc — jax top_k order)
    for (int i = tid; i < CAND; i += NTHR) {
        if (i < cnt) {
            unsigned u = __float_as_uint(cval[i]);
            unsigned s = (u & 0x80000000u) ? ~u : (u | 0x80000000u);
            ckey[i] = ((unsigned long long)s << 32) | (unsigned)(~(unsigned)cidx[i]);
        } else ckey[i] = 0ull;
    }
    __syncthreads();

    for (int ksz = 2; ksz <= CAND; ksz <<= 1)
        for (int st = ksz >> 1; st > 0; st >>= 1) {
            for (int j = tid; j < CAND; j += NTHR) {
                const int ixj = j ^ st;
                if (ixj > j) {
                    const unsigned long long a = ckey[j], b = ckey[ixj];
                    const bool desc = ((j & ksz) == 0);
                    if (desc ? (a < b) : (a > b)) { ckey[j] = b; ckey[ixj] = a; }
                }
            }
            __syncthreads();
        }

    // Phase 6: softmax over top-200
    float maxv;
    {
        const unsigned s0 = (unsigned)(ckey[0] >> 32);
        const unsigned u0 = (s0 & 0x80000000u) ? (s0 & 0x7fffffffu) : ~s0;
        maxv = __uint_as_float(u0);
    }
    float wv = 0.f;
    if (tid < MAXK) {
        const unsigned long long k = ckey[tid];
        const unsigned s = (unsigned)(k >> 32);
        const unsigned u = (s & 0x80000000u) ? (s & 0x7fffffffu) : ~s;
        const float v = __uint_as_float(u);
        const int idx = (int)(~(unsigned)k);
        wv = expf((v - maxv) * TINV);
        wgt[tid] = wv;
        lab[tid] = labels[idx];
    }
    s_red[tid] = wv;
    __syncthreads();
    for (int off = NTHR / 2; off > 0; off >>= 1) {
        if (tid < off) s_red[tid] += s_red[tid + off];
        __syncthreads();
    }
    const float inv = 1.0f / s_red[0];

    // Phase 7: 4 prefix class-histograms
    const int KS[4] = { 10, 20, 100, 200 };
    #pragma unroll
    for (int kk = 0; kk < 4; kk++) {
        for (int c = tid; c < NCLS; c += NTHR) prob[c] = 0.f;
        __syncthreads();
        if (tid < KS[kk]) atomicAdd(&prob[lab[tid]], wgt[tid] * inv);
        __syncthreads();
        float* o = out + ((size_t)kk * NQ + row) * NCLS;
        for (int c = tid; c < NCLS; c += NTHR) o[c] = prob[c];
        __syncthreads();
    }
}

// ---------------------------------------------------------------------------
// launcher: chunked GEMM on the main (captured) stream; topk for each chunk
// forks onto a non-blocking side stream via events, joins back at the end.
// Streams/events are created per call and intentionally NOT destroyed —
// destroying resources that participate in an active stream capture
// invalidates the capture; the handful of calls leak a few KB host-side.
// ---------------------------------------------------------------------------
extern "C" void kernel_launch(void* const* d_in, const int* in_sizes, int n_in,
                              void* d_out, int out_size)
{
    const float* A      = (const float*)d_in[0];   // [2048,1024]
    const float* B      = (const float*)d_in[1];   // [100000,1024]
    const int*   labels = (const int*)d_in[2];     // [100000]
    float*       out    = (float*)d_out;           // 4 x [2048,1000]

    __nv_bfloat16 *bA, *bB;
    cudaGetSymbolAddress((void**)&bA, g_bA);
    cudaGetSymbolAddress((void**)&bB, g_bB);

    cudaStream_t s1;
    cudaStreamCreateWithFlags(&s1, cudaStreamNonBlocking);
    cudaEvent_t evg[NCHUNK], evj;
    for (int c = 0; c < NCHUNK; c++)
        cudaEventCreateWithFlags(&evg[c], cudaEventDisableTiming);
    cudaEventCreateWithFlags(&evj, cudaEventDisableTiming);

    conv_bf16<<<(NQ * DIM / 8 + 255) / 256, 256>>>(A, bA, NQ * DIM / 8);
    conv_bf16<<<(NT * DIM / 8 + 255) / 256, 256>>>(B, bB, NT * DIM / 8);

    dim3 grid(MT_PER_CHUNK, (NT + BN - 1) / BN);   // 2 x 782 per chunk
    for (int c = 0; c < NCHUNK; c++) {
        gemm_mma<<<grid, 256>>>(bA, bB, c * MT_PER_CHUNK);
        cudaEventRecord(evg[c], 0);
        cudaStreamWaitEvent(s1, evg[c], 0);
        topk_kernel<<<ROWS_PER_CHUNK, NTHR, 0, s1>>>(A, B, labels, out,
                                                     c * ROWS_PER_CHUNK);
    }
    cudaEventRecord(evj, s1);
    cudaStreamWaitEvent((cudaStream_t)0, evj, 0);
}